// round 3
// baseline (speedup 1.0000x reference)
#include <cuda_runtime.h>

#define NUM_SP 1024
#define NPIX   (512 * 512)
#define NFEAT  256
#define NCLS   21

// Scratch: __device__ globals (no allocations allowed)
__device__ int g_flag;            // 0 => labels are int64 (odd words all zero), nonzero => int32
__device__ int g_counts[NUM_SP];
__device__ int g_offsets[NUM_SP];
__device__ int g_cursor[NUM_SP];
__device__ int g_sorted[NPIX];

// ---------------- Pass 0: zero histogram + flag ----------------
__global__ void zero_kernel() {
    g_counts[threadIdx.x] = 0;
    if (threadIdx.x == 0) g_flag = 0;
}

// ---------------- Pass 0b: dtype probe ----------------
// Reads only the first NPIX int32 words (in-bounds for int32 OR int64 buffers).
// If the buffer is int64 little-endian with values in [0,1024), all odd words are 0.
__global__ void probe_kernel(const int* __restrict__ sp32) {
    int i = blockIdx.x * blockDim.x + threadIdx.x;   // 0 .. NPIX/2-1
    int v = sp32[2 * i + 1];
    // warp-aggregate to cut atomics
    unsigned any = __ballot_sync(0xffffffffu, v != 0);
    if ((threadIdx.x & 31) == 0 && any) atomicOr(&g_flag, 1);
}

__device__ __forceinline__ int load_label(const int* __restrict__ sp32, int i) {
    int idx = (g_flag == 0) ? (i << 1) : i;   // int64 -> low word at 2*i
    int s = sp32[idx];
    return min(max(s, 0), NUM_SP - 1);
}

// ---------------- Pass 1: histogram of labels ----------------
__global__ void hist_kernel(const int* __restrict__ sp32) {
    int i = blockIdx.x * blockDim.x + threadIdx.x;
    if (i < NPIX) {
        int s = load_label(sp32, i);
        atomicAdd(&g_counts[s], 1);
    }
}

// ---------------- Pass 2: exclusive scan (1 CTA, 1024 threads) ----------------
__global__ void scan_kernel() {
    __shared__ int s[NUM_SP];
    int t = threadIdx.x;
    int my = g_counts[t];
    s[t] = my;
    __syncthreads();
    #pragma unroll
    for (int off = 1; off < NUM_SP; off <<= 1) {
        int v = (t >= off) ? s[t - off] : 0;
        __syncthreads();
        s[t] += v;
        __syncthreads();
    }
    int excl = s[t] - my;
    g_offsets[t] = excl;
    g_cursor[t]  = excl;
}

// ---------------- Pass 3: scatter pixel indices sorted by label ----------------
__global__ void scatter_kernel(const int* __restrict__ sp32) {
    int i = blockIdx.x * blockDim.x + threadIdx.x;
    if (i < NPIX) {
        int s = load_label(sp32, i);
        int pos = atomicAdd(&g_cursor[s], 1);
        g_sorted[pos] = i;
    }
}

// ---------------- Pass 4: per-segment gather-sum + projection ----------------
// One CTA per segment. 256 threads = 4 pixel-groups x 64 float4 lanes.
// Each pixel row is 256 floats = 64 float4 = 1024 B contiguous -> fully coalesced.
__global__ void __launch_bounds__(256) segment_kernel(
    const float* __restrict__ feat,
    const float* __restrict__ w,     // (21, 256) row-major
    float* __restrict__ out)         // (1024, 21)
{
    const int b   = blockIdx.x;
    const int tid = threadIdx.x;
    const int l   = tid & 63;   // float4 lane within the 256-float row
    const int g   = tid >> 6;   // pixel group 0..3

    const int start = g_offsets[b];
    const int cnt   = g_counts[b];

    const float4* __restrict__ f4 = (const float4*)feat;

    float4 acc = make_float4(0.f, 0.f, 0.f, 0.f);

    int p = g;
    // Unrolled x4 (stride 4 between groups) for memory-level parallelism
    for (; p + 12 < cnt; p += 16) {
        int i0 = g_sorted[start + p];
        int i1 = g_sorted[start + p + 4];
        int i2 = g_sorted[start + p + 8];
        int i3 = g_sorted[start + p + 12];
        float4 v0 = __ldg(&f4[(size_t)i0 * 64 + l]);
        float4 v1 = __ldg(&f4[(size_t)i1 * 64 + l]);
        float4 v2 = __ldg(&f4[(size_t)i2 * 64 + l]);
        float4 v3 = __ldg(&f4[(size_t)i3 * 64 + l]);
        acc.x += v0.x; acc.y += v0.y; acc.z += v0.z; acc.w += v0.w;
        acc.x += v1.x; acc.y += v1.y; acc.z += v1.z; acc.w += v1.w;
        acc.x += v2.x; acc.y += v2.y; acc.z += v2.z; acc.w += v2.w;
        acc.x += v3.x; acc.y += v3.y; acc.z += v3.z; acc.w += v3.w;
    }
    for (; p < cnt; p += 4) {
        int i0 = g_sorted[start + p];
        float4 v = __ldg(&f4[(size_t)i0 * 64 + l]);
        acc.x += v.x; acc.y += v.y; acc.z += v.z; acc.w += v.w;
    }

    // Cross-group reduce in shared memory
    __shared__ float s_part[4][NFEAT];
    __shared__ float s_nf[NFEAT];
    ((float4*)s_part[g])[l] = acc;
    __syncthreads();

    const float inv = 1.0f / (float)max(cnt, 1);
    float nf = (s_part[0][tid] + s_part[1][tid] + s_part[2][tid] + s_part[3][tid]) * inv;
    s_nf[tid] = nf;
    __syncthreads();

    // Projection: 21 dot products, warp wid handles classes c = wid, wid+8, wid+16
    const int wid  = tid >> 5;
    const int lane = tid & 31;
    for (int c = wid; c < NCLS; c += 8) {
        const float* __restrict__ wr = w + c * NFEAT;
        float part = 0.f;
        #pragma unroll
        for (int j = 0; j < 8; j++) {
            int f = lane + 32 * j;
            part += s_nf[f] * __ldg(&wr[f]);
        }
        #pragma unroll
        for (int o = 16; o > 0; o >>= 1)
            part += __shfl_down_sync(0xffffffffu, part, o);
        if (lane == 0)
            out[b * NCLS + c] = part;
    }
}

extern "C" void kernel_launch(void* const* d_in, const int* in_sizes, int n_in,
                              void* d_out, int out_size) {
    const float* feat = (const float*)d_in[0];   // (1,512,512,256) f32
    const int*   sp32 = (const int*)d_in[1];     // (512,512) int32 or int64 (probed)
    const float* w    = (const float*)d_in[2];   // (21,256) f32
    float* out = (float*)d_out;                  // (1024,21) f32

    zero_kernel<<<1, NUM_SP>>>();
    probe_kernel<<<NPIX / 2 / 256, 256>>>(sp32);
    hist_kernel<<<NPIX / 256, 256>>>(sp32);
    scan_kernel<<<1, NUM_SP>>>();
    scatter_kernel<<<NPIX / 256, 256>>>(sp32);
    segment_kernel<<<NUM_SP, 256>>>(feat, w, out);
}